// round 6
// baseline (speedup 1.0000x reference)
#include <cuda_runtime.h>
#include <mma.h>
using namespace nvcuda;

#define NN 50000
#define TOPK 32
#define INC 128
#define OUTC 64
#define BN_EPS 1e-5f

// scratch (static __device__: allocation-free per harness rules)
__device__ float g_xlin[NN * OUTC];
__device__ float g_ai[NN];
__device__ float g_aj[NN];
__device__ float g_bnsum[OUTC];
__device__ float g_bnsq[OUTC];
__device__ int   g_idx64;
__device__ float g_wht[INC * OUTC];   // W^T hi (tf32-rounded), [k][c] row-major ld=64
__device__ float g_wlt[INC * OUTC];   // W^T lo residual (tf32-rounded)

// ---------------------------------------------------------------------------
// Prep: split W^T into tf32 hi/lo, zero BN accumulators, detect index width.
// ---------------------------------------------------------------------------
__global__ void k0_prep(const float* __restrict__ lin_w, const void* __restrict__ eidx)
{
    const int tid = threadIdx.x;
    for (int i = tid; i < INC * OUTC; i += 256) {
        int c = i / INC, k = i % INC;          // lin_w is [64][128] row-major
        float w  = lin_w[i];
        float hi = wmma::__float_to_tf32(w);
        g_wht[k * OUTC + c] = hi;
        g_wlt[k * OUTC + c] = wmma::__float_to_tf32(w - hi);
    }
    if (tid < OUTC) { g_bnsum[tid] = 0.f; g_bnsq[tid] = 0.f; }
    if (tid == 0) {
        // int64 data has zero high words (all indices < 50000);
        // int32 data has words[1,3,5,7] = src[1,3,5,7] >= 1 always.
        const unsigned* w = (const unsigned*)eidx;
        g_idx64 = ((w[1] | w[3] | w[5] | w[7]) == 0u) ? 1 : 0;
    }
}

// ---------------------------------------------------------------------------
// Kernel 1: x_lin = x @ W^T via tensor cores (3xtf32 for fp32-grade accuracy).
// Block = 128 thr (4 warps), computes 64 nodes x 64 outputs. Epilogue computes
// per-node attention scalars a_i / a_j and writes xlin coalesced.
// ---------------------------------------------------------------------------
__global__ __launch_bounds__(128) void k1_gemm(
    const float* __restrict__ x, const float* __restrict__ emb,
    const float* __restrict__ att_i, const float* __restrict__ att_j,
    const float* __restrict__ att_em_i, const float* __restrict__ att_em_j)
{
    __shared__ float s_tile[64 * 68];          // ld = 68 to dodge bank conflicts
    __shared__ float s_att[4][OUTC];

    const int tid  = threadIdx.x;
    const int warp = tid >> 5;

    if (tid < OUTC) {
        s_att[0][tid] = att_i[tid];
        s_att[1][tid] = att_j[tid];
        s_att[2][tid] = att_em_i[tid];
        s_att[3][tid] = att_em_j[tid];
    }

    int mbase = blockIdx.x * 64;
    if (mbase + 64 > NN) mbase = NN - 64;      // overlap rows: identical rewrite, benign

    const float* arow = x + (size_t)(mbase + warp * 16) * INC;

    wmma::fragment<wmma::accumulator, 16, 16, 8, float> acc[4];
    #pragma unroll
    for (int i = 0; i < 4; ++i) wmma::fill_fragment(acc[i], 0.f);

    #pragma unroll 2
    for (int kt = 0; kt < INC / 8; ++kt) {
        wmma::fragment<wmma::matrix_a, 16, 16, 8, wmma::precision::tf32, wmma::row_major> a_hi, a_lo;
        wmma::load_matrix_sync(a_hi, arow + kt * 8, INC);
        #pragma unroll
        for (int i = 0; i < a_hi.num_elements; ++i) {
            float f = a_hi.x[i];
            float h = wmma::__float_to_tf32(f);
            a_hi.x[i] = h;
            a_lo.x[i] = wmma::__float_to_tf32(f - h);   // exact residual
        }
        #pragma unroll
        for (int ct = 0; ct < 4; ++ct) {
            wmma::fragment<wmma::matrix_b, 16, 16, 8, wmma::precision::tf32, wmma::row_major> b_hi, b_lo;
            wmma::load_matrix_sync(b_hi, g_wht + kt * 8 * OUTC + ct * 16, OUTC);
            wmma::load_matrix_sync(b_lo, g_wlt + kt * 8 * OUTC + ct * 16, OUTC);
            wmma::mma_sync(acc[ct], a_lo, b_hi, acc[ct]);
            wmma::mma_sync(acc[ct], a_hi, b_lo, acc[ct]);
            wmma::mma_sync(acc[ct], a_hi, b_hi, acc[ct]);
        }
    }

    #pragma unroll
    for (int ct = 0; ct < 4; ++ct)
        wmma::store_matrix_sync(&s_tile[warp * 16 * 68 + ct * 16], acc[ct], 68,
                                wmma::mem_row_major);
    __syncthreads();

    // write xlin (coalesced float4)
    for (int idx = tid; idx < 64 * 16; idx += 128) {
        int r = idx >> 4, c4 = idx & 15;
        float4 v = *(const float4*)&s_tile[r * 68 + c4 * 4];
        ((float4*)g_xlin)[(size_t)(mbase + r) * 16 + c4] = v;
    }

    // attention scalars: 2 threads per node, halves combined by shuffle
    {
        const int r = tid >> 1, half = tid & 1;
        const int n = mbase + r;
        const float* row = &s_tile[r * 68 + half * 32];
        const float* er  = emb + (size_t)n * OUTC + half * 32;
        float ai = 0.f, aj = 0.f;
        #pragma unroll 8
        for (int i = 0; i < 32; ++i) {
            float a = row[i];
            float e = er[i];
            int   c = half * 32 + i;
            ai += a * s_att[0][c] + e * s_att[2][c];
            aj += a * s_att[1][c] + e * s_att[3][c];
        }
        ai += __shfl_xor_sync(0xffffffffu, ai, 1);
        aj += __shfl_xor_sync(0xffffffffu, aj, 1);
        if (!half) { g_ai[n] = ai; g_aj[n] = aj; }
    }
}

// ---------------------------------------------------------------------------
// Kernel 2: one warp per node — segment softmax over 32 edges + self loop,
// weighted gather-aggregate of x_lin rows, bias, and BN partial sums.
// (Measured at the L2 gather roofline — unchanged.)
// ---------------------------------------------------------------------------
__global__ __launch_bounds__(256) void k2_aggr(
    const void* __restrict__ eidx, const float* __restrict__ bias,
    float* __restrict__ out)
{
    __shared__ float s_w[8][33];
    __shared__ int   s_s[8][33];
    __shared__ float s_red[8][OUTC];
    __shared__ float s_red2[8][OUTC];

    const int tid  = threadIdx.x;
    const int wid  = tid >> 5;
    const int lane = tid & 31;
    const int n    = blockIdx.x * 8 + wid;
    const int e    = n * TOPK + lane;

    int src;
    if (g_idx64) src = (int)((const long long*)eidx)[e];
    else         src = ((const int*)eidx)[e];

    const float ain = g_ai[n];
    float al = ain + g_aj[src];
    al = (al >= 0.f) ? al : 0.2f * al;
    float as = ain + g_aj[n];
    as = (as >= 0.f) ? as : 0.2f * as;

    float m = al;
    #pragma unroll
    for (int o = 16; o > 0; o >>= 1) m = fmaxf(m, __shfl_xor_sync(0xffffffffu, m, o));
    m = fmaxf(m, as);

    float w  = __expf(al - m);
    float ws = __expf(as - m);
    float sum = w;
    #pragma unroll
    for (int o = 16; o > 0; o >>= 1) sum += __shfl_xor_sync(0xffffffffu, sum, o);
    const float inv = 1.f / (sum + ws + 1e-16f);

    s_w[wid][lane] = w;
    s_s[wid][lane] = src;
    if (lane == 0) { s_w[wid][32] = ws; s_s[wid][32] = n; }
    __syncwarp();

    const float2* xl = (const float2*)g_xlin;
    float2 acc = make_float2(0.f, 0.f);
    #pragma unroll 8
    for (int k = 0; k < 33; ++k) {
        float we = s_w[wid][k];
        int   s  = s_s[wid][k];
        float2 v = xl[(size_t)s * 32 + lane];
        acc.x += we * v.x;
        acc.y += we * v.y;
    }

    float2 b = ((const float2*)bias)[lane];
    float2 r;
    r.x = acc.x * inv + b.x;
    r.y = acc.y * inv + b.y;
    ((float2*)out)[(size_t)n * 32 + lane] = r;

    s_red [wid][2 * lane]     = r.x;
    s_red [wid][2 * lane + 1] = r.y;
    s_red2[wid][2 * lane]     = r.x * r.x;
    s_red2[wid][2 * lane + 1] = r.y * r.y;
    __syncthreads();

    if (tid < OUTC) {
        float t = 0.f;
        #pragma unroll
        for (int ww = 0; ww < 8; ++ww) t += s_red[ww][tid];
        atomicAdd(&g_bnsum[tid], t);
    } else if (tid < 2 * OUTC) {
        const int c = tid - OUTC;
        float t = 0.f;
        #pragma unroll
        for (int ww = 0; ww < 8; ++ww) t += s_red2[ww][c];
        atomicAdd(&g_bnsq[c], t);
    }
}

// ---------------------------------------------------------------------------
// Kernel 3: BatchNorm (training-mode batch stats, biased var) + ReLU, in place.
// ---------------------------------------------------------------------------
__global__ __launch_bounds__(256) void k3_bn(
    float* __restrict__ out,
    const float* __restrict__ gamma, const float* __restrict__ beta)
{
    const int i = blockIdx.x * 256 + threadIdx.x;      // over float4s
    if (i >= NN * OUTC / 4) return;
    const int c0 = (i & 15) * 4;
    float4 v = ((const float4*)out)[i];
    const float invN = 1.0f / (float)NN;
    float vv[4] = {v.x, v.y, v.z, v.w};
    float rr[4];
    #pragma unroll
    for (int j = 0; j < 4; ++j) {
        int c = c0 + j;
        float mu  = g_bnsum[c] * invN;
        float var = g_bnsq[c] * invN - mu * mu;
        float sc  = gamma[c] * rsqrtf(var + BN_EPS);
        float sh  = beta[c] - mu * sc;
        rr[j] = fmaxf(vv[j] * sc + sh, 0.f);
    }
    ((float4*)out)[i] = make_float4(rr[0], rr[1], rr[2], rr[3]);
}

// ---------------------------------------------------------------------------
extern "C" void kernel_launch(void* const* d_in, const int* in_sizes, int n_in,
                              void* d_out, int out_size)
{
    const float* x     = (const float*)d_in[0];
    const float* emb   = (const float*)d_in[1];
    const void*  ei    = d_in[2];
    const float* lw    = (const float*)d_in[3];
    const float* atti  = (const float*)d_in[4];
    const float* attj  = (const float*)d_in[5];
    const float* atemi = (const float*)d_in[6];
    const float* atemj = (const float*)d_in[7];
    const float* bias  = (const float*)d_in[8];
    const float* gamma = (const float*)d_in[9];
    const float* beta  = (const float*)d_in[10];
    float* out = (float*)d_out;

    k0_prep<<<1, 256>>>(lw, ei);
    k1_gemm<<<(NN + 63) / 64, 128>>>(x, emb, atti, attj, atemi, atemj);
    k2_aggr<<<NN / 8, 256>>>(ei, bias, out);
    k3_bn<<<(NN * OUTC / 4 + 255) / 256, 256>>>(out, gamma, beta);
}

// round 9
// speedup vs baseline: 1.5155x; 1.5155x over previous
#include <cuda_runtime.h>

#define NN 50000
#define TOPK 32
#define INC 128
#define OUTC 64
#define BN_EPS 1e-5f

// scratch (static __device__: allocation-free per harness rules)
__device__ float g_xlin[NN * OUTC];
__device__ float g_ai[NN];
__device__ float g_aj[NN];
__device__ float g_bnsum[OUTC];
__device__ float g_bnsq[OUTC];
__device__ int   g_idx64;
__device__ float g_wt[INC * OUTC];    // W^T: [k][c] row-major, ld = 64

// packed f32x2 ops (Blackwell sm_10x; FFMA2 only reachable via PTX)
#define FMA_F32X2(acc, a, b) \
    asm("fma.rn.f32x2 %0, %1, %2, %0;" : "+l"(acc) : "l"(a), "l"(b))
#define DUP_F32X2(out, v) \
    asm("mov.b64 %0, {%1, %1};" : "=l"(out) : "r"(__float_as_uint(v)))
#define UNPACK_F32X2(lo, hi, in) \
    asm("mov.b64 {%0, %1}, %2;" : "=r"(lo), "=r"(hi) : "l"(in))

// ---------------------------------------------------------------------------
// Prep: transpose W to [k][c], zero BN accumulators, detect index width.
// ---------------------------------------------------------------------------
__global__ void k0_prep(const float* __restrict__ lin_w, const void* __restrict__ eidx)
{
    const int tid = threadIdx.x;
    for (int i = tid; i < INC * OUTC; i += 256) {
        int c = i >> 7, k = i & 127;          // lin_w is [64][128] row-major
        g_wt[k * OUTC + c] = lin_w[i];
    }
    if (tid < OUTC) { g_bnsum[tid] = 0.f; g_bnsq[tid] = 0.f; }
    if (tid == 0) {
        // int64 data has zero high words (all indices < 50000);
        // int32 data has words[1,3,5,7] = src[1,3,5,7] >= 1 always.
        const unsigned* w = (const unsigned*)eidx;
        g_idx64 = ((w[1] | w[3] | w[5] | w[7]) == 0u) ? 1 : 0;
    }
}

// ---------------------------------------------------------------------------
// Kernel 1: x_lin = x @ W^T, SIMT register-tiled with packed f32x2 FMAs.
// Block = 128 thr computes 128 nodes x 64 ch; thread = 8 nodes x 8 channels
// (4 channel PAIRS at c = cg*2 + 16j, j=0..3 -> conflict-free b64 W loads).
// Epilogue: coalesced xlin write + per-node attention scalars a_i / a_j.
// ---------------------------------------------------------------------------
__global__ __launch_bounds__(128) void k1_gemm(
    const float* __restrict__ x, const float* __restrict__ emb,
    const float* __restrict__ att_i, const float* __restrict__ att_j,
    const float* __restrict__ att_em_i, const float* __restrict__ att_em_j)
{
    __shared__ float s_w[INC * OUTC];     // 32 KB, [k][64]
    __shared__ float s_x[16 * 128];       // 8 KB,  [kk][node]
    __shared__ float s_att[4][OUTC];

    const int tid = threadIdx.x;

    {   // stage W (coalesced float4)
        const float4* src = (const float4*)g_wt;
        float4*       dst = (float4*)s_w;
        #pragma unroll
        for (int i = 0; i < 16; ++i) dst[tid + i * 128] = src[tid + i * 128];
    }
    if (tid < OUTC) {
        s_att[0][tid] = att_i[tid];
        s_att[1][tid] = att_j[tid];
        s_att[2][tid] = att_em_i[tid];
        s_att[3][tid] = att_em_j[tid];
    }

    int nbase = blockIdx.x * 128;
    if (nbase + 128 > NN) nbase = NN - 128;   // overlap rows: identical rewrite, benign

    const int ng  = tid >> 3;                 // 16 node-groups of 8
    const int cg  = tid & 7;                  // 8 channel-groups
    const int nd0 = ng << 3;

    unsigned long long acc[8][4];
    #pragma unroll
    for (int n = 0; n < 8; ++n)
        #pragma unroll
        for (int j = 0; j < 4; ++j) acc[n][j] = 0ULL;   // packed {+0,+0}

    const float4* xrow = (const float4*)(x + (size_t)(nbase + tid) * INC);
    float4 v0 = xrow[0], v1 = xrow[1], v2 = xrow[2], v3 = xrow[3];

    #pragma unroll 1
    for (int kc = 0; kc < 8; ++kc) {
        __syncthreads();
        s_x[ 0 * 128 + tid] = v0.x; s_x[ 1 * 128 + tid] = v0.y;
        s_x[ 2 * 128 + tid] = v0.z; s_x[ 3 * 128 + tid] = v0.w;
        s_x[ 4 * 128 + tid] = v1.x; s_x[ 5 * 128 + tid] = v1.y;
        s_x[ 6 * 128 + tid] = v1.z; s_x[ 7 * 128 + tid] = v1.w;
        s_x[ 8 * 128 + tid] = v2.x; s_x[ 9 * 128 + tid] = v2.y;
        s_x[10 * 128 + tid] = v2.z; s_x[11 * 128 + tid] = v2.w;
        s_x[12 * 128 + tid] = v3.x; s_x[13 * 128 + tid] = v3.y;
        s_x[14 * 128 + tid] = v3.z; s_x[15 * 128 + tid] = v3.w;
        __syncthreads();

        if (kc < 7) {                          // prefetch next chunk (overlaps compute)
            v0 = xrow[(kc + 1) * 4 + 0];
            v1 = xrow[(kc + 1) * 4 + 1];
            v2 = xrow[(kc + 1) * 4 + 2];
            v3 = xrow[(kc + 1) * 4 + 3];
        }

        #pragma unroll
        for (int kk = 0; kk < 16; ++kk) {
            const float4* xp = (const float4*)&s_x[kk * 128 + nd0];
            float4 xa = xp[0], xb = xp[1];
            unsigned long long xd[8];
            DUP_F32X2(xd[0], xa.x); DUP_F32X2(xd[1], xa.y);
            DUP_F32X2(xd[2], xa.z); DUP_F32X2(xd[3], xa.w);
            DUP_F32X2(xd[4], xb.x); DUP_F32X2(xd[5], xb.y);
            DUP_F32X2(xd[6], xb.z); DUP_F32X2(xd[7], xb.w);

            const unsigned long long* wp =
                (const unsigned long long*)&s_w[(kc * 16 + kk) * OUTC];
            unsigned long long w0 = wp[cg];
            unsigned long long w1 = wp[cg + 8];
            unsigned long long w2 = wp[cg + 16];
            unsigned long long w3 = wp[cg + 24];

            #pragma unroll
            for (int n = 0; n < 8; ++n) {
                FMA_F32X2(acc[n][0], xd[n], w0);
                FMA_F32X2(acc[n][1], xd[n], w1);
                FMA_F32X2(acc[n][2], xd[n], w2);
                FMA_F32X2(acc[n][3], xd[n], w3);
            }
        }
    }

    // epilogue: xlin write + attention scalars (8-lane shuffle reduce per node)
    #pragma unroll
    for (int n = 0; n < 8; ++n) {
        const int node = nbase + nd0 + n;
        float2*       xlo  = (float2*)g_xlin + (size_t)node * 32;
        const float2* erow = (const float2*)emb + (size_t)node * 32;
        float ai = 0.f, aj = 0.f;
        #pragma unroll
        for (int j = 0; j < 4; ++j) {
            unsigned lo_u, hi_u;
            UNPACK_F32X2(lo_u, hi_u, acc[n][j]);
            float lo = __uint_as_float(lo_u), hi = __uint_as_float(hi_u);
            const int c = cg * 2 + 16 * j;
            xlo[cg + 8 * j] = make_float2(lo, hi);
            float2 e = erow[cg + 8 * j];
            ai += lo * s_att[0][c] + hi * s_att[0][c + 1]
                + e.x * s_att[2][c] + e.y * s_att[2][c + 1];
            aj += lo * s_att[1][c] + hi * s_att[1][c + 1]
                + e.x * s_att[3][c] + e.y * s_att[3][c + 1];
        }
        ai += __shfl_xor_sync(0xffffffffu, ai, 1);
        ai += __shfl_xor_sync(0xffffffffu, ai, 2);
        ai += __shfl_xor_sync(0xffffffffu, ai, 4);
        aj += __shfl_xor_sync(0xffffffffu, aj, 1);
        aj += __shfl_xor_sync(0xffffffffu, aj, 2);
        aj += __shfl_xor_sync(0xffffffffu, aj, 4);
        if (cg == 0) { g_ai[node] = ai; g_aj[node] = aj; }
    }
}

// ---------------------------------------------------------------------------
// Kernel 2: one warp per node — segment softmax over 32 edges + self loop,
// weighted gather-aggregate of x_lin rows, bias, and BN partial sums.
// (At the L2 gather roofline — unchanged.)
// ---------------------------------------------------------------------------
__global__ __launch_bounds__(256) void k2_aggr(
    const void* __restrict__ eidx, const float* __restrict__ bias,
    float* __restrict__ out)
{
    __shared__ float s_w[8][33];
    __shared__ int   s_s[8][33];
    __shared__ float s_red[8][OUTC];
    __shared__ float s_red2[8][OUTC];

    const int tid  = threadIdx.x;
    const int wid  = tid >> 5;
    const int lane = tid & 31;
    const int n    = blockIdx.x * 8 + wid;
    const int e    = n * TOPK + lane;

    int src;
    if (g_idx64) src = (int)((const long long*)eidx)[e];
    else         src = ((const int*)eidx)[e];

    const float ain = g_ai[n];
    float al = ain + g_aj[src];
    al = (al >= 0.f) ? al : 0.2f * al;
    float as = ain + g_aj[n];
    as = (as >= 0.f) ? as : 0.2f * as;

    float m = al;
    #pragma unroll
    for (int o = 16; o > 0; o >>= 1) m = fmaxf(m, __shfl_xor_sync(0xffffffffu, m, o));
    m = fmaxf(m, as);

    float w  = __expf(al - m);
    float ws = __expf(as - m);
    float sum = w;
    #pragma unroll
    for (int o = 16; o > 0; o >>= 1) sum += __shfl_xor_sync(0xffffffffu, sum, o);
    const float inv = 1.f / (sum + ws + 1e-16f);

    s_w[wid][lane] = w;
    s_s[wid][lane] = src;
    if (lane == 0) { s_w[wid][32] = ws; s_s[wid][32] = n; }
    __syncwarp();

    const float2* xl = (const float2*)g_xlin;
    float2 acc = make_float2(0.f, 0.f);
    #pragma unroll 8
    for (int k = 0; k < 33; ++k) {
        float we = s_w[wid][k];
        int   s  = s_s[wid][k];
        float2 v = xl[(size_t)s * 32 + lane];
        acc.x += we * v.x;
        acc.y += we * v.y;
    }

    float2 b = ((const float2*)bias)[lane];
    float2 r;
    r.x = acc.x * inv + b.x;
    r.y = acc.y * inv + b.y;
    ((float2*)out)[(size_t)n * 32 + lane] = r;

    s_red [wid][2 * lane]     = r.x;
    s_red [wid][2 * lane + 1] = r.y;
    s_red2[wid][2 * lane]     = r.x * r.x;
    s_red2[wid][2 * lane + 1] = r.y * r.y;
    __syncthreads();

    if (tid < OUTC) {
        float t = 0.f;
        #pragma unroll
        for (int ww = 0; ww < 8; ++ww) t += s_red[ww][tid];
        atomicAdd(&g_bnsum[tid], t);
    } else if (tid < 2 * OUTC) {
        const int c = tid - OUTC;
        float t = 0.f;
        #pragma unroll
        for (int ww = 0; ww < 8; ++ww) t += s_red2[ww][c];
        atomicAdd(&g_bnsq[c], t);
    }
}

// ---------------------------------------------------------------------------
// Kernel 3: BatchNorm (training-mode batch stats, biased var) + ReLU, in place.
// ---------------------------------------------------------------------------
__global__ __launch_bounds__(256) void k3_bn(
    float* __restrict__ out,
    const float* __restrict__ gamma, const float* __restrict__ beta)
{
    const int i = blockIdx.x * 256 + threadIdx.x;      // over float4s
    if (i >= NN * OUTC / 4) return;
    const int c0 = (i & 15) * 4;
    float4 v = ((const float4*)out)[i];
    const float invN = 1.0f / (float)NN;
    float vv[4] = {v.x, v.y, v.z, v.w};
    float rr[4];
    #pragma unroll
    for (int j = 0; j < 4; ++j) {
        int c = c0 + j;
        float mu  = g_bnsum[c] * invN;
        float var = g_bnsq[c] * invN - mu * mu;
        float sc  = gamma[c] * rsqrtf(var + BN_EPS);
        float sh  = beta[c] - mu * sc;
        rr[j] = fmaxf(vv[j] * sc + sh, 0.f);
    }
    ((float4*)out)[i] = make_float4(rr[0], rr[1], rr[2], rr[3]);
}

// ---------------------------------------------------------------------------
extern "C" void kernel_launch(void* const* d_in, const int* in_sizes, int n_in,
                              void* d_out, int out_size)
{
    const float* x     = (const float*)d_in[0];
    const float* emb   = (const float*)d_in[1];
    const void*  ei    = d_in[2];
    const float* lw    = (const float*)d_in[3];
    const float* atti  = (const float*)d_in[4];
    const float* attj  = (const float*)d_in[5];
    const float* atemi = (const float*)d_in[6];
    const float* atemj = (const float*)d_in[7];
    const float* bias  = (const float*)d_in[8];
    const float* gamma = (const float*)d_in[9];
    const float* beta  = (const float*)d_in[10];
    float* out = (float*)d_out;

    k0_prep<<<1, 256>>>(lw, ei);
    k1_gemm<<<(NN + 127) / 128, 128>>>(x, emb, atti, attj, atemi, atemj);
    k2_aggr<<<NN / 8, 256>>>(ei, bias, out);
    k3_bn<<<(NN * OUTC / 4 + 255) / 256, 256>>>(out, gamma, beta);
}

// round 11
// speedup vs baseline: 1.6187x; 1.0681x over previous
#include <cuda_runtime.h>
#include <cuda_fp16.h>

#define NN 50000
#define TOPK 32
#define INC 128
#define OUTC 64
#define BN_EPS 1e-5f

// scratch (static __device__: allocation-free per harness rules)
__device__ __half2 g_xlin_h[NN * 32];   // x_lin in fp16: halves k2 gather traffic
__device__ float g_ai[NN];
__device__ float g_aj[NN];
__device__ float g_bnsum[OUTC];
__device__ float g_bnsq[OUTC];
__device__ int   g_idx64;
__device__ float g_wt[INC * OUTC];      // W^T: [k][c] row-major, ld = 64

// packed f32x2 ops (Blackwell sm_10x; FFMA2 only reachable via PTX)
#define FMA_F32X2(acc, a, b) \
    asm("fma.rn.f32x2 %0, %1, %2, %0;" : "+l"(acc) : "l"(a), "l"(b))
#define DUP_F32X2(out, v) \
    asm("mov.b64 %0, {%1, %1};" : "=l"(out) : "r"(__float_as_uint(v)))
#define UNPACK_F32X2(lo, hi, in) \
    asm("mov.b64 {%0, %1}, %2;" : "=r"(lo), "=r"(hi) : "l"(in))

// ---------------------------------------------------------------------------
// Prep: transpose W to [k][c], zero BN accumulators, detect index width.
// ---------------------------------------------------------------------------
__global__ void k0_prep(const float* __restrict__ lin_w, const void* __restrict__ eidx)
{
    const int tid = threadIdx.x;
    for (int i = tid; i < INC * OUTC; i += 256) {
        int c = i >> 7, k = i & 127;          // lin_w is [64][128] row-major
        g_wt[k * OUTC + c] = lin_w[i];
    }
    if (tid < OUTC) { g_bnsum[tid] = 0.f; g_bnsq[tid] = 0.f; }
    if (tid == 0) {
        // int64 data has zero high words (all indices < 50000);
        // int32 data has words[1,3,5,7] = src[1,3,5,7] >= 1 always.
        const unsigned* w = (const unsigned*)eidx;
        g_idx64 = ((w[1] | w[3] | w[5] | w[7]) == 0u) ? 1 : 0;
    }
}

// ---------------------------------------------------------------------------
// Kernel 1: x_lin = x @ W^T, SIMT register-tiled with packed f32x2 FMAs.
// Block = 128 thr computes 128 nodes x 64 ch; thread = 8 nodes x 8 channels
// (4 channel PAIRS at c = cg*2 + 16j, j=0..3 -> conflict-free b64 W loads).
// Epilogue: fp16 xlin write + per-node attention scalars a_i / a_j (fp32).
// ---------------------------------------------------------------------------
__global__ __launch_bounds__(128) void k1_gemm(
    const float* __restrict__ x, const float* __restrict__ emb,
    const float* __restrict__ att_i, const float* __restrict__ att_j,
    const float* __restrict__ att_em_i, const float* __restrict__ att_em_j)
{
    __shared__ float s_w[INC * OUTC];     // 32 KB, [k][64]
    __shared__ float s_x[16 * 128];       // 8 KB,  [kk][node]
    __shared__ float s_att[4][OUTC];

    const int tid = threadIdx.x;

    {   // stage W (coalesced float4)
        const float4* src = (const float4*)g_wt;
        float4*       dst = (float4*)s_w;
        #pragma unroll
        for (int i = 0; i < 16; ++i) dst[tid + i * 128] = src[tid + i * 128];
    }
    if (tid < OUTC) {
        s_att[0][tid] = att_i[tid];
        s_att[1][tid] = att_j[tid];
        s_att[2][tid] = att_em_i[tid];
        s_att[3][tid] = att_em_j[tid];
    }

    int nbase = blockIdx.x * 128;
    if (nbase + 128 > NN) nbase = NN - 128;   // overlap rows: identical rewrite, benign

    const int ng  = tid >> 3;                 // 16 node-groups of 8
    const int cg  = tid & 7;                  // 8 channel-groups
    const int nd0 = ng << 3;

    unsigned long long acc[8][4];
    #pragma unroll
    for (int n = 0; n < 8; ++n)
        #pragma unroll
        for (int j = 0; j < 4; ++j) acc[n][j] = 0ULL;   // packed {+0,+0}

    const float4* xrow = (const float4*)(x + (size_t)(nbase + tid) * INC);
    float4 v0 = xrow[0], v1 = xrow[1], v2 = xrow[2], v3 = xrow[3];

    #pragma unroll 1
    for (int kc = 0; kc < 8; ++kc) {
        __syncthreads();
        s_x[ 0 * 128 + tid] = v0.x; s_x[ 1 * 128 + tid] = v0.y;
        s_x[ 2 * 128 + tid] = v0.z; s_x[ 3 * 128 + tid] = v0.w;
        s_x[ 4 * 128 + tid] = v1.x; s_x[ 5 * 128 + tid] = v1.y;
        s_x[ 6 * 128 + tid] = v1.z; s_x[ 7 * 128 + tid] = v1.w;
        s_x[ 8 * 128 + tid] = v2.x; s_x[ 9 * 128 + tid] = v2.y;
        s_x[10 * 128 + tid] = v2.z; s_x[11 * 128 + tid] = v2.w;
        s_x[12 * 128 + tid] = v3.x; s_x[13 * 128 + tid] = v3.y;
        s_x[14 * 128 + tid] = v3.z; s_x[15 * 128 + tid] = v3.w;
        __syncthreads();

        if (kc < 7) {                          // prefetch next chunk (overlaps compute)
            v0 = xrow[(kc + 1) * 4 + 0];
            v1 = xrow[(kc + 1) * 4 + 1];
            v2 = xrow[(kc + 1) * 4 + 2];
            v3 = xrow[(kc + 1) * 4 + 3];
        }

        #pragma unroll
        for (int kk = 0; kk < 16; ++kk) {
            const float4* xp = (const float4*)&s_x[kk * 128 + nd0];
            float4 xa = xp[0], xb = xp[1];
            unsigned long long xd[8];
            DUP_F32X2(xd[0], xa.x); DUP_F32X2(xd[1], xa.y);
            DUP_F32X2(xd[2], xa.z); DUP_F32X2(xd[3], xa.w);
            DUP_F32X2(xd[4], xb.x); DUP_F32X2(xd[5], xb.y);
            DUP_F32X2(xd[6], xb.z); DUP_F32X2(xd[7], xb.w);

            const unsigned long long* wp =
                (const unsigned long long*)&s_w[(kc * 16 + kk) * OUTC];
            unsigned long long w0 = wp[cg];
            unsigned long long w1 = wp[cg + 8];
            unsigned long long w2 = wp[cg + 16];
            unsigned long long w3 = wp[cg + 24];

            #pragma unroll
            for (int n = 0; n < 8; ++n) {
                FMA_F32X2(acc[n][0], xd[n], w0);
                FMA_F32X2(acc[n][1], xd[n], w1);
                FMA_F32X2(acc[n][2], xd[n], w2);
                FMA_F32X2(acc[n][3], xd[n], w3);
            }
        }
    }

    // epilogue: fp16 xlin write + attention scalars (8-lane shuffle reduce)
    #pragma unroll
    for (int n = 0; n < 8; ++n) {
        const int node = nbase + nd0 + n;
        __half2*      xlo  = g_xlin_h + (size_t)node * 32;
        const float2* erow = (const float2*)emb + (size_t)node * 32;
        float ai = 0.f, aj = 0.f;
        #pragma unroll
        for (int j = 0; j < 4; ++j) {
            unsigned lo_u, hi_u;
            UNPACK_F32X2(lo_u, hi_u, acc[n][j]);
            float lo = __uint_as_float(lo_u), hi = __uint_as_float(hi_u);
            const int c = cg * 2 + 16 * j;
            xlo[cg + 8 * j] = __floats2half2_rn(lo, hi);
            float2 e = erow[cg + 8 * j];
            ai += lo * s_att[0][c] + hi * s_att[0][c + 1]
                + e.x * s_att[2][c] + e.y * s_att[2][c + 1];
            aj += lo * s_att[1][c] + hi * s_att[1][c + 1]
                + e.x * s_att[3][c] + e.y * s_att[3][c + 1];
        }
        ai += __shfl_xor_sync(0xffffffffu, ai, 1);
        ai += __shfl_xor_sync(0xffffffffu, ai, 2);
        ai += __shfl_xor_sync(0xffffffffu, ai, 4);
        aj += __shfl_xor_sync(0xffffffffu, aj, 1);
        aj += __shfl_xor_sync(0xffffffffu, aj, 2);
        aj += __shfl_xor_sync(0xffffffffu, aj, 4);
        if (cg == 0) { g_ai[node] = ai; g_aj[node] = aj; }
    }
}

// ---------------------------------------------------------------------------
// Kernel 2: one warp per node — segment softmax over 32 edges + self loop,
// fp16 gather (half the L2 traffic), fp32 accumulate, bias, BN partials.
// ---------------------------------------------------------------------------
__global__ __launch_bounds__(256) void k2_aggr(
    const void* __restrict__ eidx, const float* __restrict__ bias,
    float* __restrict__ out)
{
    __shared__ float s_w[8][33];
    __shared__ int   s_s[8][33];
    __shared__ float s_red[8][OUTC];
    __shared__ float s_red2[8][OUTC];

    const int tid  = threadIdx.x;
    const int wid  = tid >> 5;
    const int lane = tid & 31;
    const int n    = blockIdx.x * 8 + wid;
    const int e    = n * TOPK + lane;

    int src;
    if (g_idx64) src = (int)((const long long*)eidx)[e];
    else         src = ((const int*)eidx)[e];

    const float ain = g_ai[n];
    float al = ain + g_aj[src];
    al = (al >= 0.f) ? al : 0.2f * al;
    float as = ain + g_aj[n];
    as = (as >= 0.f) ? as : 0.2f * as;

    float m = al;
    #pragma unroll
    for (int o = 16; o > 0; o >>= 1) m = fmaxf(m, __shfl_xor_sync(0xffffffffu, m, o));
    m = fmaxf(m, as);

    float w  = __expf(al - m);
    float ws = __expf(as - m);
    float sum = w;
    #pragma unroll
    for (int o = 16; o > 0; o >>= 1) sum += __shfl_xor_sync(0xffffffffu, sum, o);
    const float inv = 1.f / (sum + ws + 1e-16f);

    s_w[wid][lane] = w;
    s_s[wid][lane] = src;
    if (lane == 0) { s_w[wid][32] = ws; s_s[wid][32] = n; }
    __syncwarp();

    float2 acc = make_float2(0.f, 0.f);
    #pragma unroll 8
    for (int k = 0; k < 33; ++k) {
        float we = s_w[wid][k];
        int   s  = s_s[wid][k];
        float2 v = __half22float2(g_xlin_h[(size_t)s * 32 + lane]);
        acc.x += we * v.x;
        acc.y += we * v.y;
    }

    float2 b = ((const float2*)bias)[lane];
    float2 r;
    r.x = acc.x * inv + b.x;
    r.y = acc.y * inv + b.y;
    ((float2*)out)[(size_t)n * 32 + lane] = r;

    s_red [wid][2 * lane]     = r.x;
    s_red [wid][2 * lane + 1] = r.y;
    s_red2[wid][2 * lane]     = r.x * r.x;
    s_red2[wid][2 * lane + 1] = r.y * r.y;
    __syncthreads();

    if (tid < OUTC) {
        float t = 0.f;
        #pragma unroll
        for (int ww = 0; ww < 8; ++ww) t += s_red[ww][tid];
        atomicAdd(&g_bnsum[tid], t);
    } else if (tid < 2 * OUTC) {
        const int c = tid - OUTC;
        float t = 0.f;
        #pragma unroll
        for (int ww = 0; ww < 8; ++ww) t += s_red2[ww][c];
        atomicAdd(&g_bnsq[c], t);
    }
}

// ---------------------------------------------------------------------------
// Kernel 3: BatchNorm (training-mode batch stats, biased var) + ReLU, in place.
// ---------------------------------------------------------------------------
__global__ __launch_bounds__(256) void k3_bn(
    float* __restrict__ out,
    const float* __restrict__ gamma, const float* __restrict__ beta)
{
    const int i = blockIdx.x * 256 + threadIdx.x;      // over float4s
    if (i >= NN * OUTC / 4) return;
    const int c0 = (i & 15) * 4;
    float4 v = ((const float4*)out)[i];
    const float invN = 1.0f / (float)NN;
    float vv[4] = {v.x, v.y, v.z, v.w};
    float rr[4];
    #pragma unroll
    for (int j = 0; j < 4; ++j) {
        int c = c0 + j;
        float mu  = g_bnsum[c] * invN;
        float var = g_bnsq[c] * invN - mu * mu;
        float sc  = gamma[c] * rsqrtf(var + BN_EPS);
        float sh  = beta[c] - mu * sc;
        rr[j] = fmaxf(vv[j] * sc + sh, 0.f);
    }
    ((float4*)out)[i] = make_float4(rr[0], rr[1], rr[2], rr[3]);
}

// ---------------------------------------------------------------------------
extern "C" void kernel_launch(void* const* d_in, const int* in_sizes, int n_in,
                              void* d_out, int out_size)
{
    const float* x     = (const float*)d_in[0];
    const float* emb   = (const float*)d_in[1];
    const void*  ei    = d_in[2];
    const float* lw    = (const float*)d_in[3];
    const float* atti  = (const float*)d_in[4];
    const float* attj  = (const float*)d_in[5];
    const float* atemi = (const float*)d_in[6];
    const float* atemj = (const float*)d_in[7];
    const float* bias  = (const float*)d_in[8];
    const float* gamma = (const float*)d_in[9];
    const float* beta  = (const float*)d_in[10];
    float* out = (float*)d_out;

    k0_prep<<<1, 256>>>(lw, ei);
    k1_gemm<<<(NN + 127) / 128, 128>>>(x, emb, atti, attj, atemi, atemj);
    k2_aggr<<<NN / 8, 256>>>(ei, bias, out);
    k3_bn<<<(NN * OUTC / 4 + 255) / 256, 256>>>(out, gamma, beta);
}